// round 5
// baseline (speedup 1.0000x reference)
#include <cuda_runtime.h>
#include <math.h>

#define LSEQ   4096
#define NFFT   8192
#define DMODEL 1024
#define ORDER  64
#define EMB    5

// ---- scratch (static device globals: allowed) ----
__device__ float  g_h3[LSEQ * ORDER];
__device__ float  g_k [DMODEL * LSEQ];
__device__ float  g_decayA[DMODEL * 64];
__device__ float  g_decayB[DMODEL * 64];
__device__ float2 g_tw[1025];                // eighth-wave twiddle table of W8192 (j in [0,1024])

// =====================================================================
// Kernel 1: implicit-filter MLP. One warp per sequence row; h exchanged
// through per-warp smem scratch (no block barriers in the hot path).
// grid 512, block 256 (8 warps = 8 rows)
// =====================================================================
#define MLP_BLOCKS 512
__global__ __launch_bounds__(256) void k_filter_mlp(
    const float* __restrict__ z, const float* __restrict__ deltas,
    const float* __restrict__ W1, const float* __restrict__ b1,
    const float* __restrict__ freq, const float* __restrict__ W2,
    const float* __restrict__ b2, const float* __restrict__ W3,
    const float* __restrict__ b3)
{
    __shared__ float sW1[ORDER * EMB], sb1[ORDER], sb2[ORDER], sb3[ORDER], sfreq[ORDER];
    __shared__ float sW2T[ORDER][ORDER + 1];   // transposed: [j][o]
    __shared__ float sW3T[ORDER][ORDER + 1];
    __shared__ float hb1[8][ORDER], hb2[8][ORDER];

    int tid = threadIdx.x;
    int wid = tid >> 5, lane = tid & 31;

    for (int i = tid; i < ORDER * EMB; i += 256) sW1[i] = W1[i];
    for (int i = tid; i < ORDER * ORDER; i += 256) {
        int o = i >> 6, j = i & 63;
        sW2T[j][o] = W2[i];
        sW3T[j][o] = W3[i];
    }
    if (tid < ORDER) { sb1[tid] = b1[tid]; sb2[tid] = b2[tid]; sb3[tid] = b3[tid]; sfreq[tid] = freq[tid]; }
    __syncthreads();

    int l = blockIdx.x * 8 + wid;
    int o0 = lane, o1 = lane + 32;

    // layer 1
    float zr[EMB];
#pragma unroll
    for (int e = 0; e < EMB; e++) zr[e] = z[l * EMB + e];   // same addr per warp: broadcast
    float a0 = sb1[o0], a1 = sb1[o1];
#pragma unroll
    for (int e = 0; e < EMB; e++) {
        a0 += zr[e] * sW1[o0 * EMB + e];
        a1 += zr[e] * sW1[o1 * EMB + e];
    }
    hb1[wid][o0] = __sinf(sfreq[o0] * a0);
    hb1[wid][o1] = __sinf(sfreq[o1] * a1);
    __syncwarp();

    // layer 2
    a0 = sb2[o0]; a1 = sb2[o1];
#pragma unroll 16
    for (int j = 0; j < ORDER; j++) {
        float hj = hb1[wid][j];                 // broadcast
        a0 += hj * sW2T[j][o0];
        a1 += hj * sW2T[j][o1];
    }
    hb2[wid][o0] = __sinf(sfreq[o0] * a0);
    hb2[wid][o1] = __sinf(sfreq[o1] * a1);
    __syncwarp();

    // layer 3
    a0 = sb3[o0]; a1 = sb3[o1];
#pragma unroll 16
    for (int j = 0; j < ORDER; j++) {
        float hj = hb2[wid][j];
        a0 += hj * sW3T[j][o0];
        a1 += hj * sW3T[j][o1];
    }
    g_h3[l * ORDER + o0] = __sinf(sfreq[o0] * a0);
    g_h3[l * ORDER + o1] = __sinf(sfreq[o1] * a1);

    // decay factorization: decay(d,l) = A[d][l>>6] * B[d][l&63]
    for (int g = blockIdx.x * 256 + tid; g < DMODEL * 64; g += MLP_BLOCKS * 256) {
        int i = g & 63;
        float a = fabsf(deltas[g >> 6]);
        g_decayA[g] = __expf(-a * (64.0f * (float)i) * (1.0f / 4095.0f));
        g_decayB[g] = __expf(-a * (float)i * (1.0f / 4095.0f));
    }
    // eighth-wave twiddle table: w[j] = exp(-2*pi*i*j/8192), j in [0,1024]
    for (int g = blockIdx.x * 256 + tid; g < 1025; g += MLP_BLOCKS * 256) {
        float ang = -2.0f * 3.14159265358979323846f * (float)g * (1.0f / 8192.0f);
        float s, c;
        sincosf(ang, &s, &c);
        g_tw[g] = make_float2(c, s);
    }
}

// =====================================================================
// Kernel 2: k[d][l] = (h3[l][:] . W4[d][:]) * decay(d,l)
// =====================================================================
__global__ __launch_bounds__(256) void k_filter_gemm(const float* __restrict__ W4)
{
    __shared__ float sh[64][65];
    __shared__ float sw[64][65];
    int lt = blockIdx.x, dt = blockIdx.y;
    int tid = threadIdx.x;

    for (int i = tid; i < 64 * 64; i += 256) {
        int row = i >> 6, col = i & 63;
        sh[row][col] = g_h3[(lt * 64 + row) * 64 + col];
        sw[row][col] = W4[(dt * 64 + row) * 64 + col];
    }
    __syncthreads();

    int tx = tid & 15, ty = tid >> 4;
    float acc[4][4];
#pragma unroll
    for (int r = 0; r < 4; r++)
#pragma unroll
        for (int c = 0; c < 4; c++) acc[r][c] = 0.0f;

#pragma unroll 8
    for (int o = 0; o < 64; o++) {
        float a[4], b[4];
#pragma unroll
        for (int r = 0; r < 4; r++) a[r] = sh[tx + 16 * r][o];
#pragma unroll
        for (int c = 0; c < 4; c++) b[c] = sw[ty + 16 * c][o];
#pragma unroll
        for (int r = 0; r < 4; r++)
#pragma unroll
            for (int c = 0; c < 4; c++) acc[r][c] += a[r] * b[c];
    }

#pragma unroll
    for (int c = 0; c < 4; c++) {
        int d = dt * 64 + ty + 16 * c;
        float dA = g_decayA[d * 64 + lt];
#pragma unroll
        for (int r = 0; r < 4; r++) {
            int li = tx + 16 * r;
            g_k[(size_t)d * LSEQ + lt * 64 + li] = acc[r][c] * dA * g_decayB[d * 64 + li];
        }
    }
}

// =====================================================================
// Kernel 3: per-channel FFT convolution.
// 8192 = 2*16*16*16; radix-2 fused into loads; 3 in-place radix-16 rounds
// in a SINGLE smem buffer (read-all -> bar -> write-all). Hermitian K
// spectrum stored half-size. smem = 110.9 KB -> 2 CTAs/SM.
// =====================================================================
#define PHI(a) ((a) + ((a) >> 4))
#define BUFSZ  8704
#define KHOFF  8704
#define TWOFF  (8704 + 4100)
#define SMEMF2 (8704 + 4100 + 1056)

__device__ __forceinline__ float2 cmul(float2 a, float2 b) {
    return make_float2(a.x * b.x - a.y * b.y, a.x * b.y + a.y * b.x);
}
__device__ __forceinline__ float2 cmulc(float2 a, float cr, float ci) {
    return make_float2(a.x * cr - a.y * ci, a.x * ci + a.y * cr);
}
__device__ __forceinline__ float2 cadd(float2 a, float2 b) { return make_float2(a.x + b.x, a.y + b.y); }
__device__ __forceinline__ float2 csub(float2 a, float2 b) { return make_float2(a.x - b.x, a.y - b.y); }
__device__ __forceinline__ float2 cmulnegi(float2 a) { return make_float2(a.y, -a.x); }

// W8192^e, e in [0,8192): eighth-wave table + reflection + quadrant rotation
__device__ __forceinline__ float2 twget(const float2* __restrict__ tw, int e) {
    int j = e & 2047;
    float2 c;
    if (j <= 1024) {
        c = tw[j];
    } else {
        float2 t = tw[2048 - j];
        c = make_float2(-t.y, -t.x);
    }
    int k = (e >> 11) & 3;
    if (k == 1)      c = make_float2(c.y, -c.x);
    else if (k == 2) c = make_float2(-c.x, -c.y);
    else if (k == 3) c = make_float2(-c.y, c.x);
    return c;
}

__device__ __forceinline__ void bf4(float2& x0, float2& x1, float2& x2, float2& x3) {
    float2 t0 = cadd(x0, x2), t1 = csub(x0, x2);
    float2 t2 = cadd(x1, x3), t3 = csub(x1, x3);
    float2 it3 = cmulnegi(t3);
    x0 = cadd(t0, t2); x2 = csub(t0, t2);
    x1 = cadd(t1, it3); x3 = csub(t1, it3);
}

#define C16 0.9238795325112867f
#define S16 0.3826834323650898f
#define R2H 0.7071067811865476f

// In-place Stockham radix-16 round, stride s = 1<<SLOG. 512 threads.
template <int SLOG, bool TW>
__device__ __forceinline__ void r16ip(float2* __restrict__ buf,
                                      const float2* __restrict__ tws, int tid)
{
    int q = tid & ((1 << SLOG) - 1);
    int p = tid >> SLOG;
    int sp = p << SLOG;

    float2 a[16];
    int lb = tid + (tid >> 4);          // PHI(tid); PHI(tid+512j) = lb + 544j
#pragma unroll
    for (int j = 0; j < 16; j++) a[j] = buf[lb + 544 * j];

    // 4 radix-4 DFTs over j2
    bf4(a[0], a[4], a[8],  a[12]);
    bf4(a[1], a[5], a[9],  a[13]);
    bf4(a[2], a[6], a[10], a[14]);
    bf4(a[3], a[7], a[11], a[15]);

    // internal twiddles W16^{j1*m}
    a[5]  = cmulc(a[5],  C16, -S16);
    a[9]  = cmulc(a[9],  R2H, -R2H);
    a[13] = cmulc(a[13], S16, -C16);
    a[6]  = cmulc(a[6],  R2H, -R2H);
    a[10] = cmulnegi(a[10]);
    a[14] = cmulc(a[14], -R2H, -R2H);
    a[7]  = cmulc(a[7],  S16, -C16);
    a[11] = cmulc(a[11], -R2H, -R2H);
    a[15] = cmulc(a[15], -C16,  S16);

    // 4 radix-4 DFTs over j1
    bf4(a[0],  a[1],  a[2],  a[3]);
    bf4(a[4],  a[5],  a[6],  a[7]);
    bf4(a[8],  a[9],  a[10], a[11]);
    bf4(a[12], a[13], a[14], a[15]);

    // apply output twiddles in registers (before the barrier)
    if (TW) {
#pragma unroll
        for (int r = 1; r < 16; r++) {
            int slot = ((r & 3) << 2) | (r >> 2);
            a[slot] = cmul(a[slot], twget(tws, r * sp));
        }
    }

    __syncthreads();                    // all reads done before any write

    int ob = q + (p << (SLOG + 4));
#pragma unroll
    for (int r = 0; r < 16; r++) {
        int slot = ((r & 3) << 2) | (r >> 2);
        int addr = ob + (r << SLOG);
        buf[addr + (addr >> 4)] = a[slot];
    }
    __syncthreads();
}

__device__ __forceinline__ void fft_rounds(float2* buf, const float2* tws, int tid)
{
    r16ip<1, true >(buf, tws, tid);     // s=2
    r16ip<5, true >(buf, tws, tid);     // s=32
    r16ip<9, false>(buf, tws, tid);     // s=512, p=0 -> twiddle-free
}

__global__ __launch_bounds__(512, 2) void k_conv(const float* __restrict__ x,
                                                 const float* __restrict__ bias,
                                                 float* __restrict__ out)
{
    extern __shared__ float2 sm[];
    float2* buf = sm;              // 8704
    float2* Kh  = sm + KHOFF;      // 4100 (uses 4097): K[0..4096], Hermitian half
    float2* tws = sm + TWOFF;      // 1056 (uses 1025)

    int tid = threadIdx.x;
    int d = blockIdx.x;

    for (int i = tid; i < 1025; i += 512) tws[i] = g_tw[i];
    __syncthreads();

    // ---- K spectrum: fused radix-2 (zero-padded) + 3 rounds ----
    const float* kg = g_k + (size_t)d * LSEQ;
#pragma unroll
    for (int it = 0; it < 8; it++) {
        int p = tid + it * 512;
        float2 v = make_float2(kg[p], 0.0f);
        float2 w = twget(tws, p);
        int o = PHI(2 * p);
        buf[o]     = v;
        buf[o + 1] = cmul(v, w);
    }
    __syncthreads();
    fft_rounds(buf, tws, tid);
    for (int i = tid; i <= 4096; i += 512) Kh[i] = buf[PHI(i)];
    __syncthreads();

    float bd = bias[d];
    const float inv = 1.0f / 8192.0f;

#pragma unroll
    for (int pr = 0; pr < 2; pr++) {
        const float* x0 = x + ((size_t)(2 * pr) * DMODEL + d) * LSEQ;
        const float* x1 = x + ((size_t)(2 * pr + 1) * DMODEL + d) * LSEQ;

        // forward FFT of packed x0 + i*x1: fused radix-2 from global
#pragma unroll
        for (int it = 0; it < 8; it++) {
            int p = tid + it * 512;
            float2 v = make_float2(x0[p], x1[p]);
            float2 w = twget(tws, p);
            int o = PHI(2 * p);
            buf[o]     = v;
            buf[o + 1] = cmul(v, w);
        }
        __syncthreads();
        fft_rounds(buf, tws, tid);      // W spectrum in buf

        // product with Hermitian K + conj + fused radix-2 (in place)
        float2 rs[8], rd[8];
#pragma unroll
        for (int it = 0; it < 8; it++) {
            int idx = tid + it * 512;                 // [0,4096)
            float2 W0 = buf[PHI(idx)];
            float2 Wh = buf[PHI(idx + 4096)];
            float2 K0 = Kh[idx];
            float2 K1 = Kh[4096 - idx];               // idx=0 -> Kh[4096] (self-conj)
            if (idx != 0) K1.y = -K1.y;               // conj
            float2 zl = cmul(W0, K0); zl.y = -zl.y;
            float2 zh = cmul(Wh, K1); zh.y = -zh.y;
            rs[it] = cadd(zl, zh);
            rd[it] = cmul(csub(zl, zh), twget(tws, idx));
        }
        __syncthreads();
#pragma unroll
        for (int it = 0; it < 8; it++) {
            int o = PHI(2 * (tid + it * 512));
            buf[o]     = rs[it];
            buf[o + 1] = rd[it];
        }
        __syncthreads();
        fft_rounds(buf, tws, tid);      // fft(conj Z) in buf

        float* o0 = out + ((size_t)(2 * pr) * DMODEL + d) * LSEQ;
        float* o1 = out + ((size_t)(2 * pr + 1) * DMODEL + d) * LSEQ;
#pragma unroll
        for (int it = 0; it < 8; it++) {
            int i = tid + it * 512;
            float2 y = buf[PHI(i)];     // ifft = conj(.)/N
            o0[i] =  y.x * inv + x0[i] * bd;
            o1[i] = -y.y * inv + x1[i] * bd;
        }
        __syncthreads();
    }
}

// =====================================================================
extern "C" void kernel_launch(void* const* d_in, const int* in_sizes, int n_in,
                              void* d_out, int out_size)
{
    (void)n_in; (void)out_size;
    const float* x = (const float*)d_in[0];
    int base = (in_sizes[1] == 1) ? 2 : 1;
    const float* z      = (const float*)d_in[base + 0];
    const float* deltas = (const float*)d_in[base + 2];
    const float* W1     = (const float*)d_in[base + 3];
    const float* b1     = (const float*)d_in[base + 4];
    const float* freq   = (const float*)d_in[base + 5];
    const float* W2     = (const float*)d_in[base + 6];
    const float* b2     = (const float*)d_in[base + 7];
    const float* W3     = (const float*)d_in[base + 8];
    const float* b3     = (const float*)d_in[base + 9];
    const float* W4     = (const float*)d_in[base + 10];
    const float* bias   = (const float*)d_in[base + 11];
    float* out = (float*)d_out;

    k_filter_mlp<<<MLP_BLOCKS, 256>>>(z, deltas, W1, b1, freq, W2, b2, W3, b3);

    dim3 g2(64, 16);
    k_filter_gemm<<<g2, 256>>>(W4);

    const int smem_bytes = SMEMF2 * (int)sizeof(float2);   // 110,880 B -> 2 CTAs/SM
    cudaFuncSetAttribute(k_conv, cudaFuncAttributeMaxDynamicSharedMemorySize, smem_bytes);
    k_conv<<<DMODEL, 512, smem_bytes>>>(x, bias, out);
}